// round 2
// baseline (speedup 1.0000x reference)
#include <cuda_runtime.h>
#include <math.h>

#define BDIM   256
#define TILE_P 32
#define ROT_LD 804          // padded rot row stride (floats)
#define KC     80           // W k-chunk per half
#define WS_LD  68           // padded W_s f-row stride (floats)
#define EPSF   1e-7f

// smem layout (float offsets)
#define OFF_ROT   0                       // 32*804      = 25728
#define OFF_WS    25728                   // 2*80*68     = 10880
#define OFF_BAND  36608                   // 7*38*32     = 8512
#define OFF_INTS  45120                   // 32*50       = 1600
#define OFF_TRIG  46720                   // 32*8        = 256
#define OFF_WTS   46976                   // 800 float4  = 3200
#define OFF_IDX   50176                   // 800 uint    = 800
#define SMEM_FLOATS 50976                 // 203904 bytes

__global__ __launch_bounds__(BDIM, 1)
void rrconv_kernel(const float* __restrict__ x,
                   const float* __restrict__ Wg,
                   const float* __restrict__ bias,
                   float* __restrict__ out)
{
    extern __shared__ float sm[];
    float*    rot_s  = sm + OFF_ROT;
    float*    W_s    = sm + OFF_WS;
    float*    band_s = sm + OFF_BAND;
    float*    ints_s = sm + OFF_INTS;
    float*    trig_s = sm + OFF_TRIG;
    float4*   wts_s  = reinterpret_cast<float4*>(sm + OFF_WTS);
    unsigned* idx_s  = reinterpret_cast<unsigned*>(sm + OFF_IDX);

    const int tid = threadIdx.x;
    const int wo0 = blockIdx.x * TILE_P;   // 0 or 32
    const int ho  = blockIdx.y;            // 0..57
    const int bb  = blockIdx.z;            // 0..7

    // ---------- Phase 0: load input band rows[ho..ho+6] cols[wo0..wo0+37] ----------
    for (int t = tid; t < 7 * 38 * 8; t += BDIM) {
        int r   = t / (38 * 8);
        int rem = t % (38 * 8);
        int cc  = rem >> 3;
        int c4  = rem & 7;
        float4 v = make_float4(0.f, 0.f, 0.f, 0.f);
        int col = wo0 + cc;
        if (col < 64)
            v = *reinterpret_cast<const float4*>(
                    x + (((size_t)(bb * 64 + ho + r) * 64 + col) * 32 + c4 * 4));
        *reinterpret_cast<float4*>(band_s + (r * 38 + cc) * 32 + c4 * 4) = v;
    }
    __syncthreads();

    // ---------- Phase 1a: intensity sums (32 px x 49 positions) ----------
    for (int t = tid; t < TILE_P * 49; t += BDIM) {
        int p = t / 49, pos = t % 49;
        int sy = pos / 7, sx = pos % 7;
        const float4* src = reinterpret_cast<const float4*>(
            band_s + (sy * 38 + p + sx) * 32);
        float4 s0 = src[0], s1 = src[1], s2 = src[2], s3 = src[3];
        float4 s4 = src[4], s5 = src[5], s6 = src[6], s7 = src[7];
        float sum = (((s0.x + s0.y) + (s0.z + s0.w)) + ((s1.x + s1.y) + (s1.z + s1.w)))
                  + (((s2.x + s2.y) + (s2.z + s2.w)) + ((s3.x + s3.y) + (s3.z + s3.w)))
                  + (((s4.x + s4.y) + (s4.z + s4.w)) + ((s5.x + s5.y) + (s5.z + s5.w)))
                  + (((s6.x + s6.y) + (s6.z + s6.w)) + ((s7.x + s7.y) + (s7.z + s7.w)));
        ints_s[p * 50 + pos] = sum;
    }
    __syncthreads();

    // ---------- Phase 1b: per-pixel angle -> affine coeffs ----------
    if (tid < TILE_P) {
        float tot = 0.f, sr = 0.f, sc = 0.f;
        #pragma unroll
        for (int i = 0; i < 7; i++) {
            #pragma unroll
            for (int j = 0; j < 7; j++) {
                float v = ints_s[tid * 50 + i * 7 + j];
                tot += v;
                sr  += v * (float)i;
                sc  += v * (float)j;
            }
        }
        float denom = tot + EPSF;
        float cr = sr / denom - 3.0f;
        float cc = sc / denom - 3.0f;
        float yv = cr, xv = cc + EPSF;
        float r2 = xv * xv + yv * yv;
        float cth, sth;
        if (r2 > 0.f) {
            float rn = sqrtf(r2);
            cth = xv / rn;   // cos(atan2(yv,xv))
            sth = yv / rn;   // sin(atan2(yv,xv))
        } else {
            cth = 1.f; sth = 0.f;
        }
        const float scale = 1.0f + EPSF;
        float xo = 3.f - 3.f * cth + 3.f * sth;
        float yo = 3.f - 3.f * sth - 3.f * cth;
        trig_s[tid * 8 + 0] = cth / scale;   // a0 (= a4)
        trig_s[tid * 8 + 1] = -sth / scale;  // a1
        trig_s[tid * 8 + 2] = xo / scale;    // a2
        trig_s[tid * 8 + 3] = sth / scale;   // a3
        trig_s[tid * 8 + 4] = yo / scale;    // a5
    }
    __syncthreads();

    // ---------- Phase 1c: bilinear descriptors (32 px x 25 positions) ----------
    for (int t = tid; t < TILE_P * 25; t += BDIM) {
        int p = t / 25, pos = t % 25;
        float A0 = trig_s[p * 8 + 0], A1 = trig_s[p * 8 + 1], A2 = trig_s[p * 8 + 2];
        float A3 = trig_s[p * 8 + 3], A5 = trig_s[p * 8 + 4];
        float xg = (float)(pos % 5 + 1);   // PAD offset into 7x7 grid
        float yg = (float)(pos / 5 + 1);
        float x_in = A0 * xg + A1 * yg + A2;
        float y_in = A3 * xg + A0 * yg + A5;
        float x0f = floorf(x_in), y0f = floorf(y_in);
        float wx1 = x_in - x0f, wx0 = 1.f - wx1;
        float wy1 = y_in - y0f, wy0 = 1.f - wy1;
        int ix0 = (int)x0f, iy0 = (int)y0f;
        int ix1 = ix0 + 1, iy1 = iy0 + 1;
        float vx0 = (ix0 >= 0 && ix0 < 7) ? 1.f : 0.f;
        float vx1 = (ix1 >= 0 && ix1 < 7) ? 1.f : 0.f;
        float vy0 = (iy0 >= 0 && iy0 < 7) ? 1.f : 0.f;
        float vy1 = (iy1 >= 0 && iy1 < 7) ? 1.f : 0.f;
        int cx0 = min(max(ix0, 0), 6), cx1 = min(max(ix1, 0), 6);
        int cy0 = min(max(iy0, 0), 6), cy1 = min(max(iy1, 0), 6);
        wts_s[t] = make_float4(wy0 * wx0 * vy0 * vx0,
                               wy0 * wx1 * vy0 * vx1,
                               wy1 * wx0 * vy1 * vx0,
                               wy1 * wx1 * vy1 * vx1);
        idx_s[t] = (unsigned)(cy0 * 7 + cx0)
                 | ((unsigned)(cy0 * 7 + cx1) << 8)
                 | ((unsigned)(cy1 * 7 + cx0) << 16)
                 | ((unsigned)(cy1 * 7 + cx1) << 24);
    }
    __syncthreads();

    // ---------- Phase 1d: materialize rotated vectors rot_s[p][pos*32+c] ----------
    for (int t = tid; t < TILE_P * 25 * 8; t += BDIM) {
        int p   = t / 200;
        int rem = t % 200;
        int pos = rem >> 3;
        int c4  = rem & 7;
        float4   w  = wts_s[p * 25 + pos];
        unsigned id = idx_s[p * 25 + pos];
        int i0 = id & 255, i1 = (id >> 8) & 255, i2 = (id >> 16) & 255, i3 = (id >> 24);
        const float4 v0 = *reinterpret_cast<const float4*>(
            band_s + ((i0 / 7) * 38 + p + (i0 % 7)) * 32 + c4 * 4);
        const float4 v1 = *reinterpret_cast<const float4*>(
            band_s + ((i1 / 7) * 38 + p + (i1 % 7)) * 32 + c4 * 4);
        const float4 v2 = *reinterpret_cast<const float4*>(
            band_s + ((i2 / 7) * 38 + p + (i2 % 7)) * 32 + c4 * 4);
        const float4 v3 = *reinterpret_cast<const float4*>(
            band_s + ((i3 / 7) * 38 + p + (i3 % 7)) * 32 + c4 * 4);
        float4 r;
        r.x = fmaf(w.x, v0.x, fmaf(w.y, v1.x, fmaf(w.z, v2.x, w.w * v3.x)));
        r.y = fmaf(w.x, v0.y, fmaf(w.y, v1.y, fmaf(w.z, v2.y, w.w * v3.y)));
        r.z = fmaf(w.x, v0.z, fmaf(w.y, v1.z, fmaf(w.z, v2.z, w.w * v3.z)));
        r.w = fmaf(w.x, v0.w, fmaf(w.y, v1.w, fmaf(w.z, v2.w, w.w * v3.w)));
        *reinterpret_cast<float4*>(rot_s + p * ROT_LD + pos * 32 + c4 * 4) = r;
    }

    // ---------- Phase 2: GEMM (32 px x 64 f x K=800), k split 2-ways ----------
    float acc[4][4];
    #pragma unroll
    for (int i = 0; i < 4; i++)
        #pragma unroll
        for (int j = 0; j < 4; j++) acc[i][j] = 0.f;

    const int ks = tid >> 7;          // k-half 0/1
    const int pg = (tid >> 4) & 7;    // pixel group (4 px each)
    const int fg = tid & 15;          // feature group (4 f each)

    for (int kc = 0; kc < 400; kc += KC) {
        __syncthreads();   // also separates phase1 -> phase2 on first iter
        // cooperative load of W chunks for both k-halves, k-major in smem
        for (int u = tid; u < 2 * 64 * KC; u += BDIM) {
            int s    = u / (64 * KC);
            int rem2 = u % (64 * KC);
            int f    = rem2 / KC;
            int kk   = rem2 % KC;
            W_s[s * (KC * WS_LD) + kk * WS_LD + f] =
                Wg[f * 800 + s * 400 + kc + kk];
        }
        __syncthreads();

        const float* rb = rot_s + pg * 4 * ROT_LD + ks * 400 + kc;
        const float* wb = W_s + ks * (KC * WS_LD) + fg * 4;
        #pragma unroll 4
        for (int kk = 0; kk < KC; kk += 4) {
            float4 a0 = *reinterpret_cast<const float4*>(rb + 0 * ROT_LD + kk);
            float4 a1 = *reinterpret_cast<const float4*>(rb + 1 * ROT_LD + kk);
            float4 a2 = *reinterpret_cast<const float4*>(rb + 2 * ROT_LD + kk);
            float4 a3 = *reinterpret_cast<const float4*>(rb + 3 * ROT_LD + kk);
            float4 w0 = *reinterpret_cast<const float4*>(wb + (kk + 0) * WS_LD);
            float4 w1 = *reinterpret_cast<const float4*>(wb + (kk + 1) * WS_LD);
            float4 w2 = *reinterpret_cast<const float4*>(wb + (kk + 2) * WS_LD);
            float4 w3 = *reinterpret_cast<const float4*>(wb + (kk + 3) * WS_LD);
            float av[4][4] = {{a0.x, a0.y, a0.z, a0.w},
                              {a1.x, a1.y, a1.z, a1.w},
                              {a2.x, a2.y, a2.z, a2.w},
                              {a3.x, a3.y, a3.z, a3.w}};
            float wv[4][4] = {{w0.x, w0.y, w0.z, w0.w},
                              {w1.x, w1.y, w1.z, w1.w},
                              {w2.x, w2.y, w2.z, w2.w},
                              {w3.x, w3.y, w3.z, w3.w}};
            #pragma unroll
            for (int i = 0; i < 4; i++)
                #pragma unroll
                for (int j = 0; j < 4; j++)
                    #pragma unroll
                    for (int k = 0; k < 4; k++)
                        acc[i][j] = fmaf(av[i][k], wv[k][j], acc[i][j]);
        }
    }

    // ---------- Phase 3: k-half reduction + store ----------
    __syncthreads();
    float* red = band_s;   // band no longer needed: 128*16 floats
    if (ks == 1) {
        #pragma unroll
        for (int i = 0; i < 4; i++)
            #pragma unroll
            for (int j = 0; j < 4; j++)
                red[(tid - 128) * 16 + i * 4 + j] = acc[i][j];
    }
    __syncthreads();
    if (ks == 0) {
        float4 bv = *reinterpret_cast<const float4*>(bias + fg * 4);
        #pragma unroll
        for (int i = 0; i < 4; i++) {
            int pw = wo0 + pg * 4 + i;
            if (pw < 58) {
                float4 o;
                o.x = acc[i][0] + red[tid * 16 + i * 4 + 0] + bv.x;
                o.y = acc[i][1] + red[tid * 16 + i * 4 + 1] + bv.y;
                o.z = acc[i][2] + red[tid * 16 + i * 4 + 2] + bv.z;
                o.w = acc[i][3] + red[tid * 16 + i * 4 + 3] + bv.w;
                *reinterpret_cast<float4*>(
                    out + ((size_t)(bb * 58 + ho) * 58 + pw) * 64 + fg * 4) = o;
            }
        }
    }
}

extern "C" void kernel_launch(void* const* d_in, const int* in_sizes, int n_in,
                              void* d_out, int out_size)
{
    const float* x    = (const float*)d_in[0];
    const float* Wg   = (const float*)d_in[1];
    const float* bias = (const float*)d_in[2];
    float* out = (float*)d_out;

    const int smem_bytes = SMEM_FLOATS * 4;
    cudaFuncSetAttribute(rrconv_kernel,
                         cudaFuncAttributeMaxDynamicSharedMemorySize, smem_bytes);
    dim3 grid(2, 58, 8);   // w-tiles, ho, batch
    rrconv_kernel<<<grid, BDIM, smem_bytes>>>(x, Wg, bias, out);
}

// round 3
// speedup vs baseline: 1.6107x; 1.6107x over previous
#include <cuda_runtime.h>
#include <math.h>

#define BDIM   256
#define TILE_P 32
#define ROT_LD 164          // 160-k chunk + pad
#define KCHUNK 160          // 5 rotation positions * 32 ch
#define NCHUNK 5
#define KHALF  80
#define EPSF   1e-7f

// smem layout (float offsets)
#define OFF_ROT   0                       // 32*164  = 5248
#define OFF_W     5248                    // 160*64  = 10240
#define OFF_BAND  15488                   // 7*38*32 = 8512
#define OFF_WTS   24000                   // 800 float4 = 3200
#define OFF_IDX   27200                   // 800 uint   = 800
#define OFF_TRIG  28000                   // 256
#define OFF_INTS  OFF_ROT                 // alias: ints dead before rot written
#define SMEM_FLOATS 28256                 // 113024 bytes -> 2 CTAs/SM

__device__ float W_t[800 * 64];           // k-major transposed weights

__global__ void transpose_W_kernel(const float* __restrict__ Wg)
{
    int idx = blockIdx.x * blockDim.x + threadIdx.x;   // over 64*800
    if (idx < 64 * 800) {
        int f = idx / 800;
        int k = idx - f * 800;
        W_t[k * 64 + f] = Wg[idx];
    }
}

__global__ __launch_bounds__(BDIM, 2)
void rrconv_kernel(const float* __restrict__ x,
                   const float* __restrict__ bias,
                   float* __restrict__ out)
{
    extern __shared__ float sm[];
    float*    rot_s  = sm + OFF_ROT;
    float*    W_s    = sm + OFF_W;
    float*    band_s = sm + OFF_BAND;
    float*    ints_s = sm + OFF_INTS;
    float*    trig_s = sm + OFF_TRIG;
    float4*   wts_s  = reinterpret_cast<float4*>(sm + OFF_WTS);
    unsigned* idx_s  = reinterpret_cast<unsigned*>(sm + OFF_IDX);

    const int tid = threadIdx.x;
    const int wo0 = blockIdx.x * TILE_P;   // 0 or 32
    const int ho  = blockIdx.y;            // 0..57
    const int bb  = blockIdx.z;            // 0..7

    // ---------- Phase 0: load input band rows[ho..ho+6] cols[wo0..wo0+37] ----------
    for (int t = tid; t < 7 * 38 * 8; t += BDIM) {
        int r   = t / (38 * 8);
        int rem = t - r * (38 * 8);
        int cc  = rem >> 3;
        int c4  = rem & 7;
        float4 v = make_float4(0.f, 0.f, 0.f, 0.f);
        int col = wo0 + cc;
        if (col < 64)
            v = *reinterpret_cast<const float4*>(
                    x + (((size_t)(bb * 64 + ho + r) * 64 + col) * 32 + c4 * 4));
        *reinterpret_cast<float4*>(band_s + (r * 38 + cc) * 32 + c4 * 4) = v;
    }
    __syncthreads();

    // ---------- Phase 1a: intensity sums (32 px x 49 positions) ----------
    for (int t = tid; t < TILE_P * 49; t += BDIM) {
        int p = t / 49, pos = t - p * 49;
        int sy = pos / 7, sx = pos - sy * 7;
        const float4* src = reinterpret_cast<const float4*>(
            band_s + (sy * 38 + p + sx) * 32);
        float4 s0 = src[0], s1 = src[1], s2 = src[2], s3 = src[3];
        float4 s4 = src[4], s5 = src[5], s6 = src[6], s7 = src[7];
        float sum = (((s0.x + s0.y) + (s0.z + s0.w)) + ((s1.x + s1.y) + (s1.z + s1.w)))
                  + (((s2.x + s2.y) + (s2.z + s2.w)) + ((s3.x + s3.y) + (s3.z + s3.w)))
                  + (((s4.x + s4.y) + (s4.z + s4.w)) + ((s5.x + s5.y) + (s5.z + s5.w)))
                  + (((s6.x + s6.y) + (s6.z + s6.w)) + ((s7.x + s7.y) + (s7.z + s7.w)));
        ints_s[p * 50 + pos] = sum;
    }
    __syncthreads();

    // ---------- Phase 1b: per-pixel angle -> affine coeffs ----------
    if (tid < TILE_P) {
        float tot = 0.f, sr = 0.f, sc = 0.f;
        #pragma unroll
        for (int i = 0; i < 7; i++) {
            #pragma unroll
            for (int j = 0; j < 7; j++) {
                float v = ints_s[tid * 50 + i * 7 + j];
                tot += v;
                sr  += v * (float)i;
                sc  += v * (float)j;
            }
        }
        float denom = tot + EPSF;
        float cr = sr / denom - 3.0f;
        float cc = sc / denom - 3.0f;
        float yv = cr, xv = cc + EPSF;
        float r2 = xv * xv + yv * yv;
        float cth, sth;
        if (r2 > 0.f) {
            float rn = sqrtf(r2);
            cth = xv / rn;
            sth = yv / rn;
        } else {
            cth = 1.f; sth = 0.f;
        }
        const float scale = 1.0f + EPSF;
        float xo = 3.f - 3.f * cth + 3.f * sth;
        float yo = 3.f - 3.f * sth - 3.f * cth;
        trig_s[tid * 8 + 0] = cth / scale;   // a0 (= a4)
        trig_s[tid * 8 + 1] = -sth / scale;  // a1
        trig_s[tid * 8 + 2] = xo / scale;    // a2
        trig_s[tid * 8 + 3] = sth / scale;   // a3
        trig_s[tid * 8 + 4] = yo / scale;    // a5
    }
    __syncthreads();

    // ---------- Phase 1c: bilinear descriptors (32 px x 25 positions) ----------
    for (int t = tid; t < TILE_P * 25; t += BDIM) {
        int p = t / 25, pos = t - p * 25;
        float A0 = trig_s[p * 8 + 0], A1 = trig_s[p * 8 + 1], A2 = trig_s[p * 8 + 2];
        float A3 = trig_s[p * 8 + 3], A5 = trig_s[p * 8 + 4];
        int py = pos / 5;
        float xg = (float)(pos - py * 5 + 1);
        float yg = (float)(py + 1);
        float x_in = A0 * xg + A1 * yg + A2;
        float y_in = A3 * xg + A0 * yg + A5;
        float x0f = floorf(x_in), y0f = floorf(y_in);
        float wx1 = x_in - x0f, wx0 = 1.f - wx1;
        float wy1 = y_in - y0f, wy0 = 1.f - wy1;
        int ix0 = (int)x0f, iy0 = (int)y0f;
        int ix1 = ix0 + 1, iy1 = iy0 + 1;
        float vx0 = (ix0 >= 0 && ix0 < 7) ? 1.f : 0.f;
        float vx1 = (ix1 >= 0 && ix1 < 7) ? 1.f : 0.f;
        float vy0 = (iy0 >= 0 && iy0 < 7) ? 1.f : 0.f;
        float vy1 = (iy1 >= 0 && iy1 < 7) ? 1.f : 0.f;
        int cx0 = min(max(ix0, 0), 6), cx1 = min(max(ix1, 0), 6);
        int cy0 = min(max(iy0, 0), 6), cy1 = min(max(iy1, 0), 6);
        wts_s[t] = make_float4(wy0 * wx0 * vy0 * vx0,
                               wy0 * wx1 * vy0 * vx1,
                               wy1 * wx0 * vy1 * vx0,
                               wy1 * wx1 * vy1 * vx1);
        idx_s[t] = (unsigned)(cy0 * 7 + cx0)
                 | ((unsigned)(cy0 * 7 + cx1) << 8)
                 | ((unsigned)(cy1 * 7 + cx0) << 16)
                 | ((unsigned)(cy1 * 7 + cx1) << 24);
    }

    // ---------- Phase 2: K chunked (5 x 160): materialize rot + GEMM ----------
    float acc[4][4];
    #pragma unroll
    for (int i = 0; i < 4; i++)
        #pragma unroll
        for (int j = 0; j < 4; j++) acc[i][j] = 0.f;

    const int ks = tid >> 7;          // k-half 0/1
    const int pg = (tid >> 4) & 7;    // pixel group (4 px each)
    const int fg = tid & 15;          // feature group (4 f each)

    for (int ch = 0; ch < NCHUNK; ch++) {
        __syncthreads();   // protect rot_s/W_s reuse (and 1c->first chunk)

        // materialize rotated vectors for 5 positions: 1280 float4 tasks
        #pragma unroll
        for (int it = 0; it < 5; it++) {
            int t   = tid + it * BDIM;
            int p   = t / 40;
            int rem = t - p * 40;
            int pos = rem >> 3;
            int c4  = rem & 7;
            int gp  = p * 25 + ch * 5 + pos;
            float4   w  = wts_s[gp];
            unsigned id = idx_s[gp];
            int i0 = id & 255, i1 = (id >> 8) & 255, i2 = (id >> 16) & 255, i3 = (id >> 24);
            const float4 v0 = *reinterpret_cast<const float4*>(
                band_s + ((i0 / 7) * 38 + p + (i0 % 7)) * 32 + c4 * 4);
            const float4 v1 = *reinterpret_cast<const float4*>(
                band_s + ((i1 / 7) * 38 + p + (i1 % 7)) * 32 + c4 * 4);
            const float4 v2 = *reinterpret_cast<const float4*>(
                band_s + ((i2 / 7) * 38 + p + (i2 % 7)) * 32 + c4 * 4);
            const float4 v3 = *reinterpret_cast<const float4*>(
                band_s + ((i3 / 7) * 38 + p + (i3 % 7)) * 32 + c4 * 4);
            float4 r;
            r.x = fmaf(w.x, v0.x, fmaf(w.y, v1.x, fmaf(w.z, v2.x, w.w * v3.x)));
            r.y = fmaf(w.x, v0.y, fmaf(w.y, v1.y, fmaf(w.z, v2.y, w.w * v3.y)));
            r.z = fmaf(w.x, v0.z, fmaf(w.y, v1.z, fmaf(w.z, v2.z, w.w * v3.z)));
            r.w = fmaf(w.x, v0.w, fmaf(w.y, v1.w, fmaf(w.z, v2.w, w.w * v3.w)));
            *reinterpret_cast<float4*>(rot_s + p * ROT_LD + pos * 32 + c4 * 4) = r;
        }

        // load W chunk (k-major, pre-transposed): pure float4 copy, coalesced
        {
            const float4* wg4 = reinterpret_cast<const float4*>(W_t + ch * KCHUNK * 64);
            float4* ws4 = reinterpret_cast<float4*>(W_s);
            #pragma unroll
            for (int it = 0; it < 10; it++)
                ws4[tid + it * BDIM] = wg4[tid + it * BDIM];
        }
        __syncthreads();

        // GEMM on this chunk: each half does KHALF=80
        const float* rb = rot_s + pg * 4 * ROT_LD + ks * KHALF;
        const float* wb = W_s + ks * KHALF * 64 + fg * 4;
        #pragma unroll 4
        for (int kk = 0; kk < KHALF; kk += 4) {
            float4 a0 = *reinterpret_cast<const float4*>(rb + 0 * ROT_LD + kk);
            float4 a1 = *reinterpret_cast<const float4*>(rb + 1 * ROT_LD + kk);
            float4 a2 = *reinterpret_cast<const float4*>(rb + 2 * ROT_LD + kk);
            float4 a3 = *reinterpret_cast<const float4*>(rb + 3 * ROT_LD + kk);
            float4 w0 = *reinterpret_cast<const float4*>(wb + (kk + 0) * 64);
            float4 w1 = *reinterpret_cast<const float4*>(wb + (kk + 1) * 64);
            float4 w2 = *reinterpret_cast<const float4*>(wb + (kk + 2) * 64);
            float4 w3 = *reinterpret_cast<const float4*>(wb + (kk + 3) * 64);
            float av[4][4] = {{a0.x, a0.y, a0.z, a0.w},
                              {a1.x, a1.y, a1.z, a1.w},
                              {a2.x, a2.y, a2.z, a2.w},
                              {a3.x, a3.y, a3.z, a3.w}};
            float wv[4][4] = {{w0.x, w0.y, w0.z, w0.w},
                              {w1.x, w1.y, w1.z, w1.w},
                              {w2.x, w2.y, w2.z, w2.w},
                              {w3.x, w3.y, w3.z, w3.w}};
            #pragma unroll
            for (int i = 0; i < 4; i++)
                #pragma unroll
                for (int j = 0; j < 4; j++)
                    #pragma unroll
                    for (int k = 0; k < 4; k++)
                        acc[i][j] = fmaf(av[i][k], wv[k][j], acc[i][j]);
        }
    }

    // ---------- Phase 3: k-half reduction + store ----------
    __syncthreads();
    float* red = band_s;   // band no longer needed: 128*16 floats
    if (ks == 1) {
        #pragma unroll
        for (int i = 0; i < 4; i++)
            #pragma unroll
            for (int j = 0; j < 4; j++)
                red[(tid - 128) * 16 + i * 4 + j] = acc[i][j];
    }
    __syncthreads();
    if (ks == 0) {
        float4 bv = *reinterpret_cast<const float4*>(bias + fg * 4);
        #pragma unroll
        for (int i = 0; i < 4; i++) {
            int pw = wo0 + pg * 4 + i;
            if (pw < 58) {
                float4 o;
                o.x = acc[i][0] + red[tid * 16 + i * 4 + 0] + bv.x;
                o.y = acc[i][1] + red[tid * 16 + i * 4 + 1] + bv.y;
                o.z = acc[i][2] + red[tid * 16 + i * 4 + 2] + bv.z;
                o.w = acc[i][3] + red[tid * 16 + i * 4 + 3] + bv.w;
                *reinterpret_cast<float4*>(
                    out + ((size_t)(bb * 58 + ho) * 58 + pw) * 64 + fg * 4) = o;
            }
        }
    }
}

extern "C" void kernel_launch(void* const* d_in, const int* in_sizes, int n_in,
                              void* d_out, int out_size)
{
    const float* x    = (const float*)d_in[0];
    const float* Wg   = (const float*)d_in[1];
    const float* bias = (const float*)d_in[2];
    float* out = (float*)d_out;

    transpose_W_kernel<<<(64 * 800 + 255) / 256, 256>>>(Wg);

    const int smem_bytes = SMEM_FLOATS * 4;
    cudaFuncSetAttribute(rrconv_kernel,
                         cudaFuncAttributeMaxDynamicSharedMemorySize, smem_bytes);
    dim3 grid(2, 58, 8);   // w-tiles, ho, batch
    rrconv_kernel<<<grid, BDIM, smem_bytes>>>(x, bias, out);
}

// round 4
// speedup vs baseline: 2.2194x; 1.3779x over previous
#include <cuda_runtime.h>
#include <math.h>

#define BDIM   256
#define TILE_P 32
#define ROT_LD 164          // 160-k chunk + pad
#define KCHUNK 160          // 5 rotation positions * 32 ch
#define NCHUNK 5
#define KHALF  80
#define EPSF   1e-7f

// smem layout (float offsets)
#define OFF_ROT   0                       // 32*164  = 5248
#define OFF_W     5248                    // 160*64  = 10240
#define OFF_BAND  15488                   // 7*38*32 = 8512
#define OFF_WTS   24000                   // 800 float4 = 3200
#define OFF_IDX   27200                   // 800 uint   = 800
#define OFF_TRIG  28000                   // 256
#define OFF_CELL  OFF_ROT                 // alias: cell sums dead before rot written
#define SMEM_FLOATS 28256                 // 113024 bytes -> 2 CTAs/SM

__device__ float W_t[800 * 64];           // k-major transposed weights

__global__ void transpose_W_kernel(const float* __restrict__ Wg)
{
    int idx = blockIdx.x * blockDim.x + threadIdx.x;   // over 64*800
    if (idx < 64 * 800) {
        int f = idx / 800;
        int k = idx - f * 800;
        W_t[k * 64 + f] = Wg[idx];
    }
}

__global__ __launch_bounds__(BDIM, 2)
void rrconv_kernel(const float* __restrict__ x,
                   const float* __restrict__ bias,
                   float* __restrict__ out)
{
    extern __shared__ float sm[];
    float*    rot_s  = sm + OFF_ROT;
    float*    W_s    = sm + OFF_W;
    float*    band_s = sm + OFF_BAND;
    float*    cell_s = sm + OFF_CELL;
    float*    trig_s = sm + OFF_TRIG;
    float4*   wts_s  = reinterpret_cast<float4*>(sm + OFF_WTS);
    unsigned* idx_s  = reinterpret_cast<unsigned*>(sm + OFF_IDX);

    const int tid = threadIdx.x;
    const int wo0 = blockIdx.x * TILE_P;   // 0 or 32
    const int ho  = blockIdx.y;            // 0..57
    const int bb  = blockIdx.z;            // 0..7

    // ---------- Phase 0: load input band rows[ho..ho+6] cols[wo0..wo0+37] ----------
    for (int t = tid; t < 7 * 38 * 8; t += BDIM) {
        int r   = t / (38 * 8);
        int rem = t - r * (38 * 8);
        int cc  = rem >> 3;
        int c4  = rem & 7;
        float4 v = make_float4(0.f, 0.f, 0.f, 0.f);
        int col = wo0 + cc;
        if (col < 64)
            v = *reinterpret_cast<const float4*>(
                    x + (((size_t)(bb * 64 + ho + r) * 64 + col) * 32 + c4 * 4));
        *reinterpret_cast<float4*>(band_s + (r * 38 + cc) * 32 + c4 * 4) = v;
    }
    __syncthreads();

    // ---------- Phase 1a: per-cell channel sums (7 x 38 cells) ----------
    for (int t = tid; t < 7 * 38; t += BDIM) {
        const float4* src = reinterpret_cast<const float4*>(band_s + t * 32);
        float4 s0 = src[0], s1 = src[1], s2 = src[2], s3 = src[3];
        float4 s4 = src[4], s5 = src[5], s6 = src[6], s7 = src[7];
        float sum = (((s0.x + s0.y) + (s0.z + s0.w)) + ((s1.x + s1.y) + (s1.z + s1.w)))
                  + (((s2.x + s2.y) + (s2.z + s2.w)) + ((s3.x + s3.y) + (s3.z + s3.w)))
                  + (((s4.x + s4.y) + (s4.z + s4.w)) + ((s5.x + s5.y) + (s5.z + s5.w)))
                  + (((s6.x + s6.y) + (s6.z + s6.w)) + ((s7.x + s7.y) + (s7.z + s7.w)));
        cell_s[t] = sum;
    }
    __syncthreads();

    // ---------- Phase 1b: per-pixel centroid -> affine coeffs ----------
    if (tid < TILE_P) {
        float tot = 0.f, sr = 0.f, sc = 0.f;
        #pragma unroll
        for (int i = 0; i < 7; i++) {
            #pragma unroll
            for (int j = 0; j < 7; j++) {
                float v = cell_s[i * 38 + tid + j];
                tot += v;
                sr  += v * (float)i;
                sc  += v * (float)j;
            }
        }
        float denom = tot + EPSF;
        float cr = sr / denom - 3.0f;
        float cc = sc / denom - 3.0f;
        float yv = cr, xv = cc + EPSF;
        float r2 = xv * xv + yv * yv;
        float cth, sth;
        if (r2 > 0.f) {
            float rn = sqrtf(r2);
            cth = xv / rn;
            sth = yv / rn;
        } else {
            cth = 1.f; sth = 0.f;
        }
        const float scale = 1.0f + EPSF;
        float xo = 3.f - 3.f * cth + 3.f * sth;
        float yo = 3.f - 3.f * sth - 3.f * cth;
        trig_s[tid * 8 + 0] = cth / scale;   // a0 (= a4)
        trig_s[tid * 8 + 1] = -sth / scale;  // a1
        trig_s[tid * 8 + 2] = xo / scale;    // a2
        trig_s[tid * 8 + 3] = sth / scale;   // a3
        trig_s[tid * 8 + 4] = yo / scale;    // a5
    }
    __syncthreads();

    // ---------- Phase 1c: bilinear descriptors (32 px x 25 positions) ----------
    for (int t = tid; t < TILE_P * 25; t += BDIM) {
        int p = t / 25, pos = t - p * 25;
        float A0 = trig_s[p * 8 + 0], A1 = trig_s[p * 8 + 1], A2 = trig_s[p * 8 + 2];
        float A3 = trig_s[p * 8 + 3], A5 = trig_s[p * 8 + 4];
        int py = pos / 5;
        float xg = (float)(pos - py * 5 + 1);
        float yg = (float)(py + 1);
        float x_in = A0 * xg + A1 * yg + A2;
        float y_in = A3 * xg + A0 * yg + A5;
        float x0f = floorf(x_in), y0f = floorf(y_in);
        float wx1 = x_in - x0f, wx0 = 1.f - wx1;
        float wy1 = y_in - y0f, wy0 = 1.f - wy1;
        int ix0 = (int)x0f, iy0 = (int)y0f;
        int ix1 = ix0 + 1, iy1 = iy0 + 1;
        float vx0 = (ix0 >= 0 && ix0 < 7) ? 1.f : 0.f;
        float vx1 = (ix1 >= 0 && ix1 < 7) ? 1.f : 0.f;
        float vy0 = (iy0 >= 0 && iy0 < 7) ? 1.f : 0.f;
        float vy1 = (iy1 >= 0 && iy1 < 7) ? 1.f : 0.f;
        int cx0 = min(max(ix0, 0), 6), cx1 = min(max(ix1, 0), 6);
        int cy0 = min(max(iy0, 0), 6), cy1 = min(max(iy1, 0), 6);
        wts_s[t] = make_float4(wy0 * wx0 * vy0 * vx0,
                               wy0 * wx1 * vy0 * vx1,
                               wy1 * wx0 * vy1 * vx0,
                               wy1 * wx1 * vy1 * vx1);
        // store band-cell offsets directly: iy*38+ix <= 234 fits in 8 bits
        idx_s[t] = (unsigned)(cy0 * 38 + cx0)
                 | ((unsigned)(cy0 * 38 + cx1) << 8)
                 | ((unsigned)(cy1 * 38 + cx0) << 16)
                 | ((unsigned)(cy1 * 38 + cx1) << 24);
    }

    // ---------- Phase 2: K chunked (5 x 160): materialize rot + GEMM ----------
    float acc[4][4];
    #pragma unroll
    for (int i = 0; i < 4; i++)
        #pragma unroll
        for (int j = 0; j < 4; j++) acc[i][j] = 0.f;

    const int ks = tid >> 7;          // k-half 0/1
    const int pg = (tid >> 4) & 7;    // pixel group (4 px each)
    const int fg = tid & 15;          // feature group (4 f each)

    #pragma unroll 1
    for (int ch = 0; ch < NCHUNK; ch++) {
        __syncthreads();   // protect rot_s/W_s reuse (and 1c->first chunk)

        // materialize rotated vectors for 5 positions: 1280 float4 tasks
        #pragma unroll
        for (int it = 0; it < 5; it++) {
            int t   = tid + it * BDIM;
            int p   = t / 40;
            int rem = t - p * 40;
            int pos = rem >> 3;
            int c4  = rem & 7;
            int gp  = p * 25 + ch * 5 + pos;
            float4   w  = wts_s[gp];
            unsigned id = idx_s[gp];
            int base = p * 32 + c4 * 4;
            const float4 v0 = *reinterpret_cast<const float4*>(
                band_s + (id & 255) * 32 + base);
            const float4 v1 = *reinterpret_cast<const float4*>(
                band_s + ((id >> 8) & 255) * 32 + base);
            const float4 v2 = *reinterpret_cast<const float4*>(
                band_s + ((id >> 16) & 255) * 32 + base);
            const float4 v3 = *reinterpret_cast<const float4*>(
                band_s + (id >> 24) * 32 + base);
            float4 r;
            r.x = fmaf(w.x, v0.x, fmaf(w.y, v1.x, fmaf(w.z, v2.x, w.w * v3.x)));
            r.y = fmaf(w.x, v0.y, fmaf(w.y, v1.y, fmaf(w.z, v2.y, w.w * v3.y)));
            r.z = fmaf(w.x, v0.z, fmaf(w.y, v1.z, fmaf(w.z, v2.z, w.w * v3.z)));
            r.w = fmaf(w.x, v0.w, fmaf(w.y, v1.w, fmaf(w.z, v2.w, w.w * v3.w)));
            *reinterpret_cast<float4*>(rot_s + p * ROT_LD + pos * 32 + c4 * 4) = r;
        }

        // load W chunk (k-major, pre-transposed): pure float4 copy, coalesced
        {
            const float4* wg4 = reinterpret_cast<const float4*>(W_t + ch * KCHUNK * 64);
            float4* ws4 = reinterpret_cast<float4*>(W_s);
            #pragma unroll
            for (int it = 0; it < 10; it++)
                ws4[tid + it * BDIM] = wg4[tid + it * BDIM];
        }
        __syncthreads();

        // GEMM on this chunk: each half does KHALF=80, fully unrolled so
        // ptxas software-pipelines the LDS across k-steps.
        const float* rb = rot_s + pg * 4 * ROT_LD + ks * KHALF;
        const float* wb = W_s + ks * KHALF * 64 + fg * 4;
        #pragma unroll
        for (int kk = 0; kk < KHALF; kk += 4) {
            float4 a0 = *reinterpret_cast<const float4*>(rb + 0 * ROT_LD + kk);
            float4 a1 = *reinterpret_cast<const float4*>(rb + 1 * ROT_LD + kk);
            float4 a2 = *reinterpret_cast<const float4*>(rb + 2 * ROT_LD + kk);
            float4 a3 = *reinterpret_cast<const float4*>(rb + 3 * ROT_LD + kk);
            float4 w0 = *reinterpret_cast<const float4*>(wb + (kk + 0) * 64);
            float4 w1 = *reinterpret_cast<const float4*>(wb + (kk + 1) * 64);
            float4 w2 = *reinterpret_cast<const float4*>(wb + (kk + 2) * 64);
            float4 w3 = *reinterpret_cast<const float4*>(wb + (kk + 3) * 64);
            float av[4][4] = {{a0.x, a0.y, a0.z, a0.w},
                              {a1.x, a1.y, a1.z, a1.w},
                              {a2.x, a2.y, a2.z, a2.w},
                              {a3.x, a3.y, a3.z, a3.w}};
            float wv[4][4] = {{w0.x, w0.y, w0.z, w0.w},
                              {w1.x, w1.y, w1.z, w1.w},
                              {w2.x, w2.y, w2.z, w2.w},
                              {w3.x, w3.y, w3.z, w3.w}};
            #pragma unroll
            for (int i = 0; i < 4; i++)
                #pragma unroll
                for (int j = 0; j < 4; j++)
                    #pragma unroll
                    for (int k = 0; k < 4; k++)
                        acc[i][j] = fmaf(av[i][k], wv[k][j], acc[i][j]);
        }
    }

    // ---------- Phase 3: k-half reduction + store ----------
    __syncthreads();
    float* red = band_s;   // band no longer needed: 128*16 floats
    if (ks == 1) {
        #pragma unroll
        for (int i = 0; i < 4; i++)
            #pragma unroll
            for (int j = 0; j < 4; j++)
                red[(tid - 128) * 16 + i * 4 + j] = acc[i][j];
    }
    __syncthreads();
    if (ks == 0) {
        float4 bv = *reinterpret_cast<const float4*>(bias + fg * 4);
        #pragma unroll
        for (int i = 0; i < 4; i++) {
            int pw = wo0 + pg * 4 + i;
            if (pw < 58) {
                float4 o;
                o.x = acc[i][0] + red[tid * 16 + i * 4 + 0] + bv.x;
                o.y = acc[i][1] + red[tid * 16 + i * 4 + 1] + bv.y;
                o.z = acc[i][2] + red[tid * 16 + i * 4 + 2] + bv.z;
                o.w = acc[i][3] + red[tid * 16 + i * 4 + 3] + bv.w;
                *reinterpret_cast<float4*>(
                    out + ((size_t)(bb * 58 + ho) * 58 + pw) * 64 + fg * 4) = o;
            }
        }
    }
}

extern "C" void kernel_launch(void* const* d_in, const int* in_sizes, int n_in,
                              void* d_out, int out_size)
{
    const float* x    = (const float*)d_in[0];
    const float* Wg   = (const float*)d_in[1];
    const float* bias = (const float*)d_in[2];
    float* out = (float*)d_out;

    transpose_W_kernel<<<(64 * 800 + 255) / 256, 256>>>(Wg);

    const int smem_bytes = SMEM_FLOATS * 4;
    cudaFuncSetAttribute(rrconv_kernel,
                         cudaFuncAttributeMaxDynamicSharedMemorySize, smem_bytes);
    dim3 grid(2, 58, 8);   // w-tiles, ho, batch
    rrconv_kernel<<<grid, BDIM, smem_bytes>>>(x, bias, out);
}

// round 5
// speedup vs baseline: 2.2879x; 1.0309x over previous
#include <cuda_runtime.h>
#include <math.h>

#define BDIM   256
#define TILE_P 32
#define ROT_LD 164          // 160-k chunk + pad
#define KCHUNK 160          // 5 rotation positions * 32 ch
#define NCHUNK 5
#define KQ     40           // K per k-split-quarter per chunk
#define EPSF   1e-7f

// smem layout (float offsets)
#define OFF_ROT   0                       // 32*164  = 5248
#define OFF_W     5248                    // 160*64  = 10240
#define OFF_BAND  15488                   // 7*38*32 = 8512
#define OFF_WTS   24000                   // 800 float4 = 3200
#define OFF_IDX   27200                   // 800 uint   = 800
#define OFF_TRIG  28000                   // 256
#define OFF_CELL  OFF_ROT                 // alias: cell sums dead before rot written
#define SMEM_FLOATS 28256                 // 113024 bytes -> 2 CTAs/SM

__device__ float W_t[800 * 64];           // k-major transposed weights

__global__ void transpose_W_kernel(const float* __restrict__ Wg)
{
    int idx = blockIdx.x * blockDim.x + threadIdx.x;   // over 64*800
    if (idx < 64 * 800) {
        int f = idx / 800;
        int k = idx - f * 800;
        W_t[k * 64 + f] = Wg[idx];
    }
}

__global__ __launch_bounds__(BDIM, 2)
void rrconv_kernel(const float* __restrict__ x,
                   const float* __restrict__ bias,
                   float* __restrict__ out)
{
    extern __shared__ float sm[];
    float*    rot_s  = sm + OFF_ROT;
    float*    W_s    = sm + OFF_W;
    float*    band_s = sm + OFF_BAND;
    float*    cell_s = sm + OFF_CELL;
    float*    trig_s = sm + OFF_TRIG;
    float4*   wts_s  = reinterpret_cast<float4*>(sm + OFF_WTS);
    unsigned* idx_s  = reinterpret_cast<unsigned*>(sm + OFF_IDX);

    const int tid = threadIdx.x;
    const int wo0 = blockIdx.x * TILE_P;   // 0 or 32
    const int ho  = blockIdx.y;            // 0..57
    const int bb  = blockIdx.z;            // 0..7

    // ---------- Phase 0: load input band rows[ho..ho+6] cols[wo0..wo0+37] ----------
    for (int t = tid; t < 7 * 38 * 8; t += BDIM) {
        int r   = t / (38 * 8);
        int rem = t - r * (38 * 8);
        int cc  = rem >> 3;
        int c4  = rem & 7;
        float4 v = make_float4(0.f, 0.f, 0.f, 0.f);
        int col = wo0 + cc;
        if (col < 64)
            v = *reinterpret_cast<const float4*>(
                    x + (((size_t)(bb * 64 + ho + r) * 64 + col) * 32 + c4 * 4));
        *reinterpret_cast<float4*>(band_s + (r * 38 + cc) * 32 + c4 * 4) = v;
    }
    __syncthreads();

    // ---------- Phase 1a: per-cell channel sums (7 x 38 cells) ----------
    for (int t = tid; t < 7 * 38; t += BDIM) {
        const float4* src = reinterpret_cast<const float4*>(band_s + t * 32);
        float4 s0 = src[0], s1 = src[1], s2 = src[2], s3 = src[3];
        float4 s4 = src[4], s5 = src[5], s6 = src[6], s7 = src[7];
        float sum = (((s0.x + s0.y) + (s0.z + s0.w)) + ((s1.x + s1.y) + (s1.z + s1.w)))
                  + (((s2.x + s2.y) + (s2.z + s2.w)) + ((s3.x + s3.y) + (s3.z + s3.w)))
                  + (((s4.x + s4.y) + (s4.z + s4.w)) + ((s5.x + s5.y) + (s5.z + s5.w)))
                  + (((s6.x + s6.y) + (s6.z + s6.w)) + ((s7.x + s7.y) + (s7.z + s7.w)));
        cell_s[t] = sum;
    }
    __syncthreads();

    // ---------- Phase 1b: per-pixel centroid -> affine coeffs ----------
    if (tid < TILE_P) {
        float tot = 0.f, sr = 0.f, sc = 0.f;
        #pragma unroll
        for (int i = 0; i < 7; i++) {
            #pragma unroll
            for (int j = 0; j < 7; j++) {
                float v = cell_s[i * 38 + tid + j];
                tot += v;
                sr  += v * (float)i;
                sc  += v * (float)j;
            }
        }
        float denom = tot + EPSF;
        float cr = sr / denom - 3.0f;
        float cc = sc / denom - 3.0f;
        float yv = cr, xv = cc + EPSF;
        float r2 = xv * xv + yv * yv;
        float cth, sth;
        if (r2 > 0.f) {
            float rn = sqrtf(r2);
            cth = xv / rn;
            sth = yv / rn;
        } else {
            cth = 1.f; sth = 0.f;
        }
        const float scale = 1.0f + EPSF;
        float xo = 3.f - 3.f * cth + 3.f * sth;
        float yo = 3.f - 3.f * sth - 3.f * cth;
        trig_s[tid * 8 + 0] = cth / scale;   // a0 (= a4)
        trig_s[tid * 8 + 1] = -sth / scale;  // a1
        trig_s[tid * 8 + 2] = xo / scale;    // a2
        trig_s[tid * 8 + 3] = sth / scale;   // a3
        trig_s[tid * 8 + 4] = yo / scale;    // a5
    }
    __syncthreads();

    // ---------- Phase 1c: bilinear descriptors (32 px x 25 positions) ----------
    for (int t = tid; t < TILE_P * 25; t += BDIM) {
        int p = t / 25, pos = t - p * 25;
        float A0 = trig_s[p * 8 + 0], A1 = trig_s[p * 8 + 1], A2 = trig_s[p * 8 + 2];
        float A3 = trig_s[p * 8 + 3], A5 = trig_s[p * 8 + 4];
        int py = pos / 5;
        float xg = (float)(pos - py * 5 + 1);
        float yg = (float)(py + 1);
        float x_in = A0 * xg + A1 * yg + A2;
        float y_in = A3 * xg + A0 * yg + A5;
        float x0f = floorf(x_in), y0f = floorf(y_in);
        float wx1 = x_in - x0f, wx0 = 1.f - wx1;
        float wy1 = y_in - y0f, wy0 = 1.f - wy1;
        int ix0 = (int)x0f, iy0 = (int)y0f;
        int ix1 = ix0 + 1, iy1 = iy0 + 1;
        float vx0 = (ix0 >= 0 && ix0 < 7) ? 1.f : 0.f;
        float vx1 = (ix1 >= 0 && ix1 < 7) ? 1.f : 0.f;
        float vy0 = (iy0 >= 0 && iy0 < 7) ? 1.f : 0.f;
        float vy1 = (iy1 >= 0 && iy1 < 7) ? 1.f : 0.f;
        int cx0 = min(max(ix0, 0), 6), cx1 = min(max(ix1, 0), 6);
        int cy0 = min(max(iy0, 0), 6), cy1 = min(max(iy1, 0), 6);
        wts_s[t] = make_float4(wy0 * wx0 * vy0 * vx0,
                               wy0 * wx1 * vy0 * vx1,
                               wy1 * wx0 * vy1 * vx0,
                               wy1 * wx1 * vy1 * vx1);
        // store band-cell offsets directly: iy*38+ix <= 234 fits in 8 bits
        idx_s[t] = (unsigned)(cy0 * 38 + cx0)
                 | ((unsigned)(cy0 * 38 + cx1) << 8)
                 | ((unsigned)(cy1 * 38 + cx0) << 16)
                 | ((unsigned)(cy1 * 38 + cx1) << 24);
    }

    // ---------- Phase 2: K chunked (5 x 160): materialize rot + GEMM ----------
    // microtile: 8 px x 4 f per thread, k-split 4 ways
    float acc[8][4];
    #pragma unroll
    for (int i = 0; i < 8; i++)
        #pragma unroll
        for (int j = 0; j < 4; j++) acc[i][j] = 0.f;

    const int ks = tid >> 6;          // k-quarter 0..3
    const int pg = (tid >> 4) & 3;    // pixel group (8 px each)
    const int fg = tid & 15;          // feature group (4 f each)

    #pragma unroll 1
    for (int ch = 0; ch < NCHUNK; ch++) {
        __syncthreads();   // protect rot_s/W_s reuse (and 1c->first chunk)

        // materialize rotated vectors for 5 positions: 1280 float4 tasks
        #pragma unroll
        for (int it = 0; it < 5; it++) {
            int t   = tid + it * BDIM;
            int p   = t / 40;
            int rem = t - p * 40;
            int pos = rem >> 3;
            int c4  = rem & 7;
            int gp  = p * 25 + ch * 5 + pos;
            float4   w  = wts_s[gp];
            unsigned id = idx_s[gp];
            int base = p * 32 + c4 * 4;
            const float4 v0 = *reinterpret_cast<const float4*>(
                band_s + (id & 255) * 32 + base);
            const float4 v1 = *reinterpret_cast<const float4*>(
                band_s + ((id >> 8) & 255) * 32 + base);
            const float4 v2 = *reinterpret_cast<const float4*>(
                band_s + ((id >> 16) & 255) * 32 + base);
            const float4 v3 = *reinterpret_cast<const float4*>(
                band_s + (id >> 24) * 32 + base);
            float4 r;
            r.x = fmaf(w.x, v0.x, fmaf(w.y, v1.x, fmaf(w.z, v2.x, w.w * v3.x)));
            r.y = fmaf(w.x, v0.y, fmaf(w.y, v1.y, fmaf(w.z, v2.y, w.w * v3.y)));
            r.z = fmaf(w.x, v0.z, fmaf(w.y, v1.z, fmaf(w.z, v2.z, w.w * v3.z)));
            r.w = fmaf(w.x, v0.w, fmaf(w.y, v1.w, fmaf(w.z, v2.w, w.w * v3.w)));
            *reinterpret_cast<float4*>(rot_s + p * ROT_LD + pos * 32 + c4 * 4) = r;
        }

        // load W chunk (k-major, pre-transposed): pure float4 copy, coalesced
        {
            const float4* wg4 = reinterpret_cast<const float4*>(W_t + ch * KCHUNK * 64);
            float4* ws4 = reinterpret_cast<float4*>(W_s);
            #pragma unroll
            for (int it = 0; it < 10; it++)
                ws4[tid + it * BDIM] = wg4[tid + it * BDIM];
        }
        __syncthreads();

        // GEMM on this chunk: each quarter does KQ=40, fully unrolled
        const float* rb = rot_s + pg * 8 * ROT_LD + ks * KQ;
        const float* wb = W_s + ks * KQ * 64 + fg * 4;
        #pragma unroll
        for (int kk = 0; kk < KQ; kk += 4) {
            float4 w0 = *reinterpret_cast<const float4*>(wb + (kk + 0) * 64);
            float4 w1 = *reinterpret_cast<const float4*>(wb + (kk + 1) * 64);
            float4 w2 = *reinterpret_cast<const float4*>(wb + (kk + 2) * 64);
            float4 w3 = *reinterpret_cast<const float4*>(wb + (kk + 3) * 64);
            float wv[4][4] = {{w0.x, w0.y, w0.z, w0.w},
                              {w1.x, w1.y, w1.z, w1.w},
                              {w2.x, w2.y, w2.z, w2.w},
                              {w3.x, w3.y, w3.z, w3.w}};
            #pragma unroll
            for (int i = 0; i < 8; i++) {
                float4 a = *reinterpret_cast<const float4*>(rb + i * ROT_LD + kk);
                #pragma unroll
                for (int j = 0; j < 4; j++)
                    acc[i][j] = fmaf(a.x, wv[0][j],
                                fmaf(a.y, wv[1][j],
                                fmaf(a.z, wv[2][j],
                                fmaf(a.w, wv[3][j], acc[i][j]))));
            }
        }
    }

    // ---------- Phase 3: 4-way k reduction + store ----------
    __syncthreads();
    float* red = band_s;   // band no longer needed: 3*64*32 floats = 6144
    if (ks != 0) {
        float* dst = red + ((ks - 1) * 64 + (tid & 63)) * 32;
        #pragma unroll
        for (int i = 0; i < 8; i++) {
            float4 v = make_float4(acc[i][0], acc[i][1], acc[i][2], acc[i][3]);
            *reinterpret_cast<float4*>(dst + i * 4) = v;
        }
    }
    __syncthreads();
    if (ks == 0) {
        float4 bv = *reinterpret_cast<const float4*>(bias + fg * 4);
        const float* r1 = red + (0 * 64 + tid) * 32;
        const float* r2 = red + (1 * 64 + tid) * 32;
        const float* r3 = red + (2 * 64 + tid) * 32;
        #pragma unroll
        for (int i = 0; i < 8; i++) {
            int pw = wo0 + pg * 8 + i;
            if (pw < 58) {
                float4 p1 = *reinterpret_cast<const float4*>(r1 + i * 4);
                float4 p2 = *reinterpret_cast<const float4*>(r2 + i * 4);
                float4 p3 = *reinterpret_cast<const float4*>(r3 + i * 4);
                float4 o;
                o.x = ((acc[i][0] + p1.x) + (p2.x + p3.x)) + bv.x;
                o.y = ((acc[i][1] + p1.y) + (p2.y + p3.y)) + bv.y;
                o.z = ((acc[i][2] + p1.z) + (p2.z + p3.z)) + bv.z;
                o.w = ((acc[i][3] + p1.w) + (p2.w + p3.w)) + bv.w;
                *reinterpret_cast<float4*>(
                    out + ((size_t)(bb * 58 + ho) * 58 + pw) * 64 + fg * 4) = o;
            }
        }
    }
}

extern "C" void kernel_launch(void* const* d_in, const int* in_sizes, int n_in,
                              void* d_out, int out_size)
{
    const float* x    = (const float*)d_in[0];
    const float* Wg   = (const float*)d_in[1];
    const float* bias = (const float*)d_in[2];
    float* out = (float*)d_out;

    transpose_W_kernel<<<(64 * 800 + 255) / 256, 256>>>(Wg);

    const int smem_bytes = SMEM_FLOATS * 4;
    cudaFuncSetAttribute(rrconv_kernel,
                         cudaFuncAttributeMaxDynamicSharedMemorySize, smem_bytes);
    dim3 grid(2, 58, 8);   // w-tiles, ho, batch
    rrconv_kernel<<<grid, BDIM, smem_bytes>>>(x, bias, out);
}

// round 6
// speedup vs baseline: 2.3693x; 1.0356x over previous
#include <cuda_runtime.h>
#include <math.h>

#define BDIM   256
#define TILE_P 32
#define ROT_LD 164          // 160-k chunk + pad
#define KCHUNK 160          // 5 rotation positions * 32 ch
#define NCHUNK 5
#define KQ     40           // K per k-split-quarter per chunk
#define EPSF   1e-7f

// smem layout (float offsets)
#define OFF_ROT0  0                       // 32*164 = 5248
#define OFF_ROT1  5248                    // 32*164 = 5248
#define OFF_BAND  10496                   // 7*38*32 = 8512
#define OFF_WTS   19008                   // 800 float4 = 3200
#define OFF_IDX   22208                   // 800 uint   = 800
#define OFF_TRIG  23008                   // 64
#define OFF_CELL  OFF_ROT0                // alias: cell sums dead before rot written
#define SMEM_FLOATS 23072                 // 92288 bytes -> 2 CTAs/SM

__device__ float W_t[800 * 64];           // k-major transposed weights

__global__ void transpose_W_kernel(const float* __restrict__ Wg)
{
    int idx = blockIdx.x * blockDim.x + threadIdx.x;   // over 64*800
    if (idx < 64 * 800) {
        int f = idx / 800;
        int k = idx - f * 800;
        W_t[k * 64 + f] = Wg[idx];
    }
}

// materialize 5 rotation positions (chunk ch) into rotbuf
__device__ __forceinline__ void materialize_chunk(
    float* __restrict__ rotbuf, const float* __restrict__ band_s,
    const float4* __restrict__ wts_s, const unsigned* __restrict__ idx_s,
    int ch, int tid)
{
    #pragma unroll
    for (int it = 0; it < 5; it++) {
        int t   = tid + it * BDIM;
        int p   = t / 40;
        int rem = t - p * 40;
        int pos = rem >> 3;
        int c4  = rem & 7;
        int gp  = p * 25 + ch * 5 + pos;
        float4   w  = wts_s[gp];
        unsigned id = idx_s[gp];
        int base = p * 32 + c4 * 4;
        const float4 v0 = *reinterpret_cast<const float4*>(
            band_s + (id & 255) * 32 + base);
        const float4 v1 = *reinterpret_cast<const float4*>(
            band_s + ((id >> 8) & 255) * 32 + base);
        const float4 v2 = *reinterpret_cast<const float4*>(
            band_s + ((id >> 16) & 255) * 32 + base);
        const float4 v3 = *reinterpret_cast<const float4*>(
            band_s + (id >> 24) * 32 + base);
        float4 r;
        r.x = fmaf(w.x, v0.x, fmaf(w.y, v1.x, fmaf(w.z, v2.x, w.w * v3.x)));
        r.y = fmaf(w.x, v0.y, fmaf(w.y, v1.y, fmaf(w.z, v2.y, w.w * v3.y)));
        r.z = fmaf(w.x, v0.z, fmaf(w.y, v1.z, fmaf(w.z, v2.z, w.w * v3.z)));
        r.w = fmaf(w.x, v0.w, fmaf(w.y, v1.w, fmaf(w.z, v2.w, w.w * v3.w)));
        *reinterpret_cast<float4*>(rotbuf + p * ROT_LD + pos * 32 + c4 * 4) = r;
    }
}

__global__ __launch_bounds__(BDIM, 2)
void rrconv_kernel(const float* __restrict__ x,
                   const float* __restrict__ bias,
                   float* __restrict__ out)
{
    extern __shared__ float sm[];
    float*    rot0   = sm + OFF_ROT0;
    float*    rot1   = sm + OFF_ROT1;
    float*    band_s = sm + OFF_BAND;
    float*    cell_s = sm + OFF_CELL;
    float*    trig_s = sm + OFF_TRIG;
    float4*   wts_s  = reinterpret_cast<float4*>(sm + OFF_WTS);
    unsigned* idx_s  = reinterpret_cast<unsigned*>(sm + OFF_IDX);

    const int tid = threadIdx.x;
    const int wo0 = blockIdx.x * TILE_P;   // 0 or 32
    const int ho  = blockIdx.y;            // 0..57
    const int bb  = blockIdx.z;            // 0..7

    // ---------- Phase 0: load input band rows[ho..ho+6] cols[wo0..wo0+37] ----------
    for (int t = tid; t < 7 * 38 * 8; t += BDIM) {
        int r   = t / (38 * 8);
        int rem = t - r * (38 * 8);
        int cc  = rem >> 3;
        int c4  = rem & 7;
        float4 v = make_float4(0.f, 0.f, 0.f, 0.f);
        int col = wo0 + cc;
        if (col < 64)
            v = *reinterpret_cast<const float4*>(
                    x + (((size_t)(bb * 64 + ho + r) * 64 + col) * 32 + c4 * 4));
        *reinterpret_cast<float4*>(band_s + (r * 38 + cc) * 32 + c4 * 4) = v;
    }
    __syncthreads();

    // ---------- Phase 1a: per-cell channel sums (7 x 38 cells) ----------
    for (int t = tid; t < 7 * 38; t += BDIM) {
        const float4* src = reinterpret_cast<const float4*>(band_s + t * 32);
        float4 s0 = src[0], s1 = src[1], s2 = src[2], s3 = src[3];
        float4 s4 = src[4], s5 = src[5], s6 = src[6], s7 = src[7];
        float sum = (((s0.x + s0.y) + (s0.z + s0.w)) + ((s1.x + s1.y) + (s1.z + s1.w)))
                  + (((s2.x + s2.y) + (s2.z + s2.w)) + ((s3.x + s3.y) + (s3.z + s3.w)))
                  + (((s4.x + s4.y) + (s4.z + s4.w)) + ((s5.x + s5.y) + (s5.z + s5.w)))
                  + (((s6.x + s6.y) + (s6.z + s6.w)) + ((s7.x + s7.y) + (s7.z + s7.w)));
        cell_s[t] = sum;
    }
    __syncthreads();

    // ---------- Phase 1b: per-pixel centroid -> affine coeffs ----------
    if (tid < TILE_P) {
        float tot = 0.f, sr = 0.f, sc = 0.f;
        #pragma unroll
        for (int i = 0; i < 7; i++) {
            #pragma unroll
            for (int j = 0; j < 7; j++) {
                float v = cell_s[i * 38 + tid + j];
                tot += v;
                sr  += v * (float)i;
                sc  += v * (float)j;
            }
        }
        float denom = tot + EPSF;
        float cr = sr / denom - 3.0f;
        float cc = sc / denom - 3.0f;
        float yv = cr, xv = cc + EPSF;
        float r2 = xv * xv + yv * yv;
        float cth, sth;
        if (r2 > 0.f) {
            float rn = sqrtf(r2);
            cth = xv / rn;
            sth = yv / rn;
        } else {
            cth = 1.f; sth = 0.f;
        }
        const float scale = 1.0f + EPSF;
        float xo = 3.f - 3.f * cth + 3.f * sth;
        float yo = 3.f - 3.f * sth - 3.f * cth;
        trig_s[tid] = 0.f;   // touch to keep layout (unused slot)
        // pack coeffs into cell_s tail region? keep dedicated trig via wts scratch:
    }
    // store coeffs in registers via shared staging (use trig area within wts_s tail)
    __syncthreads();

    // recompute coeffs into a small shared array (reuse idx_s tail is unsafe; use sm+OFF_TRIG..+64? too small for 32*8)
    // -> instead: compute 1b directly into 1c below using shuffle-free shared staging
    // Simpler: redo 1b storing into cell_s[300..] (cell region is 266 floats; rot0 has 5248) — safe.
    if (tid < TILE_P) {
        float tot = 0.f, sr = 0.f, sc = 0.f;
        #pragma unroll
        for (int i = 0; i < 7; i++) {
            #pragma unroll
            for (int j = 0; j < 7; j++) {
                float v = cell_s[i * 38 + tid + j];
                tot += v;
                sr  += v * (float)i;
                sc  += v * (float)j;
            }
        }
        float denom = tot + EPSF;
        float cr = sr / denom - 3.0f;
        float cc = sc / denom - 3.0f;
        float yv = cr, xv = cc + EPSF;
        float r2 = xv * xv + yv * yv;
        float cth, sth;
        if (r2 > 0.f) {
            float rn = sqrtf(r2);
            cth = xv / rn;
            sth = yv / rn;
        } else {
            cth = 1.f; sth = 0.f;
        }
        const float scale = 1.0f + EPSF;
        float xo = 3.f - 3.f * cth + 3.f * sth;
        float yo = 3.f - 3.f * sth - 3.f * cth;
        float* tb = cell_s + 300;          // 32*8 = 256 floats, within rot0 buffer
        tb[tid * 8 + 0] = cth / scale;     // a0 (= a4)
        tb[tid * 8 + 1] = -sth / scale;    // a1
        tb[tid * 8 + 2] = xo / scale;      // a2
        tb[tid * 8 + 3] = sth / scale;     // a3
        tb[tid * 8 + 4] = yo / scale;      // a5
    }
    __syncthreads();

    // ---------- Phase 1c: bilinear descriptors (32 px x 25 positions) ----------
    {
        const float* tb = cell_s + 300;
        for (int t = tid; t < TILE_P * 25; t += BDIM) {
            int p = t / 25, pos = t - p * 25;
            float A0 = tb[p * 8 + 0], A1 = tb[p * 8 + 1], A2 = tb[p * 8 + 2];
            float A3 = tb[p * 8 + 3], A5 = tb[p * 8 + 4];
            int py = pos / 5;
            float xg = (float)(pos - py * 5 + 1);
            float yg = (float)(py + 1);
            float x_in = A0 * xg + A1 * yg + A2;
            float y_in = A3 * xg + A0 * yg + A5;
            float x0f = floorf(x_in), y0f = floorf(y_in);
            float wx1 = x_in - x0f, wx0 = 1.f - wx1;
            float wy1 = y_in - y0f, wy0 = 1.f - wy1;
            int ix0 = (int)x0f, iy0 = (int)y0f;
            int ix1 = ix0 + 1, iy1 = iy0 + 1;
            float vx0 = (ix0 >= 0 && ix0 < 7) ? 1.f : 0.f;
            float vx1 = (ix1 >= 0 && ix1 < 7) ? 1.f : 0.f;
            float vy0 = (iy0 >= 0 && iy0 < 7) ? 1.f : 0.f;
            float vy1 = (iy1 >= 0 && iy1 < 7) ? 1.f : 0.f;
            int cx0 = min(max(ix0, 0), 6), cx1 = min(max(ix1, 0), 6);
            int cy0 = min(max(iy0, 0), 6), cy1 = min(max(iy1, 0), 6);
            wts_s[t] = make_float4(wy0 * wx0 * vy0 * vx0,
                                   wy0 * wx1 * vy0 * vx1,
                                   wy1 * wx0 * vy1 * vx0,
                                   wy1 * wx1 * vy1 * vx1);
            idx_s[t] = (unsigned)(cy0 * 38 + cx0)
                     | ((unsigned)(cy0 * 38 + cx1) << 8)
                     | ((unsigned)(cy1 * 38 + cx0) << 16)
                     | ((unsigned)(cy1 * 38 + cx1) << 24);
        }
    }
    __syncthreads();

    // ---------- Phase 2: pipelined materialize + GEMM (W direct from gmem) ----------
    float acc[8][4];
    #pragma unroll
    for (int i = 0; i < 8; i++)
        #pragma unroll
        for (int j = 0; j < 4; j++) acc[i][j] = 0.f;

    const int ks = tid >> 6;          // k-quarter 0..3
    const int pg = (tid >> 4) & 3;    // pixel group (8 px each)
    const int fg = tid & 15;          // feature group (4 f each)

    // prologue: materialize chunk 0 into rot0
    materialize_chunk(rot0, band_s, wts_s, idx_s, 0, tid);
    __syncthreads();

    #pragma unroll 1
    for (int ch = 0; ch < NCHUNK; ch++) {
        float* cur = (ch & 1) ? rot1 : rot0;
        float* nxt = (ch & 1) ? rot0 : rot1;
        if (ch + 1 < NCHUNK)
            materialize_chunk(nxt, band_s, wts_s, idx_s, ch + 1, tid);

        // GEMM on chunk ch: KQ=40 per quarter, W streamed from gmem (L1/L2 hit)
        const float* rb = cur + pg * 8 * ROT_LD + ks * KQ;
        const float* wb = W_t + (ch * KCHUNK + ks * KQ) * 64 + fg * 4;
        #pragma unroll
        for (int kk = 0; kk < KQ; kk += 4) {
            float4 w0 = *reinterpret_cast<const float4*>(wb + (kk + 0) * 64);
            float4 w1 = *reinterpret_cast<const float4*>(wb + (kk + 1) * 64);
            float4 w2 = *reinterpret_cast<const float4*>(wb + (kk + 2) * 64);
            float4 w3 = *reinterpret_cast<const float4*>(wb + (kk + 3) * 64);
            float wv[4][4] = {{w0.x, w0.y, w0.z, w0.w},
                              {w1.x, w1.y, w1.z, w1.w},
                              {w2.x, w2.y, w2.z, w2.w},
                              {w3.x, w3.y, w3.z, w3.w}};
            #pragma unroll
            for (int i = 0; i < 8; i++) {
                float4 a = *reinterpret_cast<const float4*>(rb + i * ROT_LD + kk);
                #pragma unroll
                for (int j = 0; j < 4; j++)
                    acc[i][j] = fmaf(a.x, wv[0][j],
                                fmaf(a.y, wv[1][j],
                                fmaf(a.z, wv[2][j],
                                fmaf(a.w, wv[3][j], acc[i][j]))));
            }
        }
        __syncthreads();   // next buffer complete; cur free for overwrite
    }

    // ---------- Phase 3: 4-way k reduction + store ----------
    float* red = band_s;   // band no longer needed: 3*64*32 floats = 6144
    if (ks != 0) {
        float* dst = red + ((ks - 1) * 64 + (tid & 63)) * 32;
        #pragma unroll
        for (int i = 0; i < 8; i++) {
            float4 v = make_float4(acc[i][0], acc[i][1], acc[i][2], acc[i][3]);
            *reinterpret_cast<float4*>(dst + i * 4) = v;
        }
    }
    __syncthreads();
    if (ks == 0) {
        float4 bv = *reinterpret_cast<const float4*>(bias + fg * 4);
        const float* r1 = red + (0 * 64 + tid) * 32;
        const float* r2 = red + (1 * 64 + tid) * 32;
        const float* r3 = red + (2 * 64 + tid) * 32;
        #pragma unroll
        for (int i = 0; i < 8; i++) {
            int pw = wo0 + pg * 8 + i;
            if (pw < 58) {
                float4 p1 = *reinterpret_cast<const float4*>(r1 + i * 4);
                float4 p2 = *reinterpret_cast<const float4*>(r2 + i * 4);
                float4 p3 = *reinterpret_cast<const float4*>(r3 + i * 4);
                float4 o;
                o.x = ((acc[i][0] + p1.x) + (p2.x + p3.x)) + bv.x;
                o.y = ((acc[i][1] + p1.y) + (p2.y + p3.y)) + bv.y;
                o.z = ((acc[i][2] + p1.z) + (p2.z + p3.z)) + bv.z;
                o.w = ((acc[i][3] + p1.w) + (p2.w + p3.w)) + bv.w;
                *reinterpret_cast<float4*>(
                    out + ((size_t)(bb * 58 + ho) * 58 + pw) * 64 + fg * 4) = o;
            }
        }
    }
}

extern "C" void kernel_launch(void* const* d_in, const int* in_sizes, int n_in,
                              void* d_out, int out_size)
{
    const float* x    = (const float*)d_in[0];
    const float* Wg   = (const float*)d_in[1];
    const float* bias = (const float*)d_in[2];
    float* out = (float*)d_out;

    transpose_W_kernel<<<(64 * 800 + 255) / 256, 256>>>(Wg);

    const int smem_bytes = SMEM_FLOATS * 4;
    cudaFuncSetAttribute(rrconv_kernel,
                         cudaFuncAttributeMaxDynamicSharedMemorySize, smem_bytes);
    dim3 grid(2, 58, 8);   // w-tiles, ho, batch
    rrconv_kernel<<<grid, BDIM, smem_bytes>>>(x, bias, out);
}